// round 10
// baseline (speedup 1.0000x reference)
#include <cuda_runtime.h>
#include <cstdint>
#include <cstddef>

#define N_USER 100000
#define N_ITEM 150000
#define NTOT   250000
#define D      64
#define NNZ    1250000
#define BATCH  16384
#define GD     16
#define DSTATE 8
#define DCONV  4
#define DINNER 32
#define DTRANK 1
#define NDBC   (DTRANK + 2 * DSTATE)   // 17
#define TEMP   0.8f
#define CAP    64
#define NWORDS ((NTOT + 31) / 32)

// ---------------------------------------------------------------------------
// Device scratch (no cudaMalloc allowed)
// ---------------------------------------------------------------------------
__device__ float    g_embA[(size_t)NTOT * D];
__device__ int      g_cnt[NTOT];
__device__ float2   g_bucket[(size_t)NTOT * CAP];
__device__ unsigned g_need1[NWORDS];
__device__ unsigned g_need2[NWORDS];
__device__ int      g_rowlist[NTOT];
__device__ int      g_nrows;

__device__ __forceinline__ bool testbit(const unsigned* bm, int i) {
    return (bm[i >> 5] >> (i & 31)) & 1u;
}
// set bit; if newly set, append row to rowlist
__device__ __forceinline__ void mark_and_list(int i) {
    unsigned old = atomicOr(&g_need1[i >> 5], 1u << (i & 31));
    if (!((old >> (i & 31)) & 1u)) {
        int pos = atomicAdd(&g_nrows, 1);
        g_rowlist[pos] = i;
    }
}

// ---------------------------------------------------------------------------
// Init
// ---------------------------------------------------------------------------
__global__ void init_kernel() {
    int i = blockIdx.x * blockDim.x + threadIdx.x;
    if (i < NTOT)   g_cnt[i] = 0;
    if (i < NWORDS) { g_need1[i] = 0; g_need2[i] = 0; }
    if (i == 0)     g_nrows = 0;
}

__global__ void mark2_kernel(const int* __restrict__ node_ids) {
    int i = blockIdx.x * blockDim.x + threadIdx.x;
    if (i >= BATCH) return;
    int nid = node_ids[i];
    atomicOr(&g_need2[nid >> 5], 1u << (nid & 31));
    mark_and_list(nid);
}

__global__ void mark1_kernel(const int* __restrict__ erow,
                             const int* __restrict__ ecol) {
    int i = blockIdx.x * blockDim.x + threadIdx.x;
    if (i >= NNZ / 4) return;
    int4 r = reinterpret_cast<const int4*>(erow)[i];
    int4 c = reinterpret_cast<const int4*>(ecol)[i];
    if (testbit(g_need2, r.x)) mark_and_list(c.x);
    if (testbit(g_need2, r.y)) mark_and_list(c.y);
    if (testbit(g_need2, r.z)) mark_and_list(c.z);
    if (testbit(g_need2, r.w)) mark_and_list(c.w);
}

// Bucket scatter (bitmap-filtered), 4 edges per thread.
__global__ void bucket_kernel(const int*   __restrict__ erow,
                              const int*   __restrict__ ecol,
                              const float* __restrict__ eval) {
    int i = blockIdx.x * blockDim.x + threadIdx.x;
    if (i >= NNZ / 4) return;
    int4   r = reinterpret_cast<const int4*>(erow)[i];
    int4   c = reinterpret_cast<const int4*>(ecol)[i];
    float4 v = reinterpret_cast<const float4*>(eval)[i];
    if (testbit(g_need1, r.x)) {
        int p = atomicAdd(&g_cnt[r.x], 1);
        if (p < CAP) g_bucket[(size_t)r.x * CAP + p] = make_float2(__int_as_float(c.x), v.x);
    }
    if (testbit(g_need1, r.y)) {
        int p = atomicAdd(&g_cnt[r.y], 1);
        if (p < CAP) g_bucket[(size_t)r.y * CAP + p] = make_float2(__int_as_float(c.y), v.y);
    }
    if (testbit(g_need1, r.z)) {
        int p = atomicAdd(&g_cnt[r.z], 1);
        if (p < CAP) g_bucket[(size_t)r.z * CAP + p] = make_float2(__int_as_float(c.z), v.z);
    }
    if (testbit(g_need1, r.w)) {
        int p = atomicAdd(&g_cnt[r.w], 1);
        if (p < CAP) g_bucket[(size_t)r.w * CAP + p] = make_float2(__int_as_float(c.w), v.w);
    }
}

// ---------------------------------------------------------------------------
// Layer-1 fused gather + L2-normalize over the DENSE rowlist (grid-stride).
// 16 lanes per row; x4-unrolled edge loop, 4 accumulators, float4 edge loads
// (bucket rows 512B-aligned -> 2 edges per 16B load).
// ---------------------------------------------------------------------------
#define GN_GRID 2048

__global__ __launch_bounds__(256)
void gather_norm1_kernel(const float* __restrict__ user,
                         const float* __restrict__ item) {
    const int nrows = g_nrows;
    const unsigned q = (threadIdx.x & 15u) * 4u;
    int g = blockIdx.x * 16 + (threadIdx.x >> 4);

    for (; g < nrows; g += GN_GRID * 16) {
        int r = g_rowlist[g];
        int deg = g_cnt[r]; if (deg > CAP) deg = CAP;
        const float2* eb  = g_bucket + (size_t)r * CAP;
        const float4* eb4 = reinterpret_cast<const float4*>(eb);

        float4 a0 = make_float4(0.f, 0.f, 0.f, 0.f);
        float4 a1 = make_float4(0.f, 0.f, 0.f, 0.f);
        float4 a2 = make_float4(0.f, 0.f, 0.f, 0.f);
        float4 a3 = make_float4(0.f, 0.f, 0.f, 0.f);
        int p = 0;
        for (; p + 3 < deg; p += 4) {
            float4 e01 = eb4[p >> 1];
            float4 e23 = eb4[(p >> 1) + 1];
            int c0 = __float_as_int(e01.x), c1 = __float_as_int(e01.z);
            int c2 = __float_as_int(e23.x), c3 = __float_as_int(e23.z);
            const float* s0 = (c0 < N_USER) ? (user + (size_t)c0 * D)
                                            : (item + (size_t)(c0 - N_USER) * D);
            const float* s1 = (c1 < N_USER) ? (user + (size_t)c1 * D)
                                            : (item + (size_t)(c1 - N_USER) * D);
            const float* s2 = (c2 < N_USER) ? (user + (size_t)c2 * D)
                                            : (item + (size_t)(c2 - N_USER) * D);
            const float* s3 = (c3 < N_USER) ? (user + (size_t)c3 * D)
                                            : (item + (size_t)(c3 - N_USER) * D);
            float4 v0 = *reinterpret_cast<const float4*>(s0 + q);
            float4 v1 = *reinterpret_cast<const float4*>(s1 + q);
            float4 v2 = *reinterpret_cast<const float4*>(s2 + q);
            float4 v3 = *reinterpret_cast<const float4*>(s3 + q);
            a0.x += e01.y * v0.x; a0.y += e01.y * v0.y; a0.z += e01.y * v0.z; a0.w += e01.y * v0.w;
            a1.x += e01.w * v1.x; a1.y += e01.w * v1.y; a1.z += e01.w * v1.z; a1.w += e01.w * v1.w;
            a2.x += e23.y * v2.x; a2.y += e23.y * v2.y; a2.z += e23.y * v2.z; a2.w += e23.y * v2.w;
            a3.x += e23.w * v3.x; a3.y += e23.w * v3.y; a3.z += e23.w * v3.z; a3.w += e23.w * v3.w;
        }
        for (; p < deg; p++) {
            float2 e = eb[p];
            int c = __float_as_int(e.x);
            const float* sp = (c < N_USER) ? (user + (size_t)c * D)
                                           : (item + (size_t)(c - N_USER) * D);
            float4 s = *reinterpret_cast<const float4*>(sp + q);
            a0.x += e.y * s.x; a0.y += e.y * s.y; a0.z += e.y * s.z; a0.w += e.y * s.w;
        }
        float4 acc = make_float4(a0.x + a1.x + a2.x + a3.x,
                                 a0.y + a1.y + a2.y + a3.y,
                                 a0.z + a1.z + a2.z + a3.z,
                                 a0.w + a1.w + a2.w + a3.w);

        float ss = acc.x * acc.x + acc.y * acc.y + acc.z * acc.z + acc.w * acc.w;
#pragma unroll
        for (int o = 8; o > 0; o >>= 1)
            ss += __shfl_xor_sync(0xffffffffu, ss, o, 16);
        float inv = 1.0f / fmaxf(sqrtf(ss), 1e-12f);
        acc.x *= inv; acc.y *= inv; acc.z *= inv; acc.w *= inv;

        *reinterpret_cast<float4*>(g_embA + (size_t)r * D + q) = acc;
    }
}

// ---------------------------------------------------------------------------
// Fused layer-2 gather + Mamba + LayerNorm + softmax fusion (4 threads/node).
// ---------------------------------------------------------------------------
__device__ __forceinline__ float softplus_f(float x) {
    return (x > 20.f) ? x : log1pf(__expf(x));
}
__device__ __forceinline__ float silu_f(float x) {
    return x / (1.f + __expf(-x));
}
__device__ __forceinline__ float grp4_sum(float x) {
    x += __shfl_xor_sync(0xffffffffu, x, 1);
    x += __shfl_xor_sync(0xffffffffu, x, 2);
    return x;
}

#define NPB 32   // nodes per block

__global__ __launch_bounds__(128)
void mamba_fuse_kernel(const float* __restrict__ user,
                       const float* __restrict__ item,
                       const int*   __restrict__ node_ids,
                       const float* __restrict__ down_w,
                       const float* __restrict__ in_proj_w,
                       const float* __restrict__ conv_w,
                       const float* __restrict__ conv_b,
                       const float* __restrict__ x_proj_w,
                       const float* __restrict__ dt_proj_w,
                       const float* __restrict__ dt_proj_b,
                       const float* __restrict__ A_log,
                       const float* __restrict__ D_param,
                       const float* __restrict__ out_proj_w,
                       const float* __restrict__ ln_g,
                       const float* __restrict__ ln_b,
                       const float* __restrict__ to_logit_w,
                       const float* __restrict__ to_logit_b,
                       float* __restrict__ out) {
    __shared__ __align__(16) float s_embB[NPB * 64];
    __shared__ float s_down[GD * 64];
    __shared__ float s_inproj[2 * DINNER * GD];
    __shared__ float s_convw[DINNER * DCONV];
    __shared__ float s_convb[DINNER];
    __shared__ float s_xproj[NDBC * DINNER];
    __shared__ float s_dtw[DINNER];
    __shared__ float s_dtb[DINNER];
    __shared__ float s_A[DINNER * DSTATE];
    __shared__ float s_D[DINNER];
    __shared__ float s_outproj[GD * DINNER];
    __shared__ float s_lng[GD], s_lnb[GD], s_tlw[GD];
    __shared__ float s_tlb;
    __shared__ float s_w[NPB * 3];
    __shared__ int   s_nid[NPB];

    const int tid = threadIdx.x;
    for (int i = tid; i < GD * 64; i += 128)            s_down[i]   = down_w[i];
    for (int i = tid; i < 2 * DINNER * GD; i += 128)    s_inproj[i] = in_proj_w[i];
    for (int i = tid; i < DINNER * DCONV; i += 128)     s_convw[i]  = conv_w[i];
    for (int i = tid; i < NDBC * DINNER; i += 128)      s_xproj[i]  = x_proj_w[i];
    for (int i = tid; i < DINNER * DSTATE; i += 128)    s_A[i]      = -__expf(A_log[i]);
    for (int i = tid; i < GD * DINNER; i += 128)        s_outproj[i]= out_proj_w[i];
    if (tid < DINNER) {
        s_convb[tid] = conv_b[tid];
        s_dtw[tid]   = dt_proj_w[tid];
        s_dtb[tid]   = dt_proj_b[tid];
        s_D[tid]     = D_param[tid];
    }
    if (tid < GD) {
        s_lng[tid] = ln_g[tid];
        s_lnb[tid] = ln_b[tid];
        s_tlw[tid] = to_logit_w[tid];
    }
    if (tid == 0) s_tlb = to_logit_b[0];
    __syncthreads();

    const int nl  = tid >> 2;
    const int k   = tid & 3;
    const int b   = blockIdx.x * NPB + nl;
    const int nid = node_ids[b];
    if (k == 0) s_nid[nl] = nid;

    // ---- fused layer-2 gather: embB quarter (16 cols) -> shared -------------
    {
        float4 e2[4];
#pragma unroll
        for (int u = 0; u < 4; u++) e2[u] = make_float4(0.f, 0.f, 0.f, 0.f);
        int deg = g_cnt[nid]; if (deg > CAP) deg = CAP;
        const float2* eb = g_bucket + (size_t)nid * CAP;
        for (int p = 0; p < deg; p++) {
            float2 e = eb[p];
            int   c = __float_as_int(e.x);
            float v = e.y;
            const float4* src = reinterpret_cast<const float4*>(
                g_embA + (size_t)c * D + k * 16);
#pragma unroll
            for (int u = 0; u < 4; u++) {
                float4 s = src[u];
                e2[u].x += v * s.x; e2[u].y += v * s.y;
                e2[u].z += v * s.z; e2[u].w += v * s.w;
            }
        }
        float ss = 0.f;
#pragma unroll
        for (int u = 0; u < 4; u++)
            ss += e2[u].x * e2[u].x + e2[u].y * e2[u].y
                + e2[u].z * e2[u].z + e2[u].w * e2[u].w;
        ss = grp4_sum(ss);
        float inv = 1.0f / fmaxf(sqrtf(ss), 1e-12f);
#pragma unroll
        for (int u = 0; u < 4; u++) {
            e2[u].x *= inv; e2[u].y *= inv; e2[u].z *= inv; e2[u].w *= inv;
            *reinterpret_cast<float4*>(&s_embB[nl * 64 + k * 16 + u * 4]) = e2[u];
        }
    }
    __syncwarp();

    // ---- g = seq @ down_w.T --------------------------------------------------
    float gg[3][GD];
#pragma unroll
    for (int l = 0; l < 3; l++)
#pragma unroll
        for (int j = 0; j < GD; j++) gg[l][j] = 0.f;

#pragma unroll
    for (int l = 0; l < 3; l++) {
        float4 rq[4];
        if (l == 2) {
#pragma unroll
            for (int u = 0; u < 4; u++)
                rq[u] = *reinterpret_cast<const float4*>(&s_embB[nl * 64 + k * 16 + u * 4]);
        } else {
            const float* row;
            if (l == 0)
                row = (nid < N_USER) ? (user + (size_t)nid * D)
                                     : (item + (size_t)(nid - N_USER) * D);
            else
                row = g_embA + (size_t)nid * D;
            const float4* r4 = reinterpret_cast<const float4*>(row + k * 16);
#pragma unroll
            for (int u = 0; u < 4; u++) rq[u] = r4[u];
        }
#pragma unroll
        for (int u = 0; u < 4; u++) {
            float4 sv = rq[u];
            int colbase = k * 16 + u * 4;
#pragma unroll
            for (int j = 0; j < GD; j++) {
                const float* dwj = &s_down[j * 64 + colbase];
                gg[l][j] += sv.x * dwj[0] + sv.y * dwj[1]
                          + sv.z * dwj[2] + sv.w * dwj[3];
            }
        }
    }
#pragma unroll
    for (int l = 0; l < 3; l++)
#pragma unroll
        for (int j = 0; j < GD; j++) gg[l][j] = grp4_sum(gg[l][j]);

    // ---- dbc over own 8 d-channels (xc cached), then reduce -------------------
    float dbc[3][NDBC];
    float xcr[3][8];
#pragma unroll
    for (int l = 0; l < 3; l++)
#pragma unroll
        for (int r = 0; r < NDBC; r++) dbc[l][r] = 0.f;

#pragma unroll
    for (int i = 0; i < 8; i++) {
        int d = k * 8 + i;
        float xr0 = 0.f, xr1 = 0.f, xr2 = 0.f;
#pragma unroll
        for (int j = 0; j < GD; j++) {
            float w = s_inproj[d * GD + j];
            xr0 += gg[0][j] * w; xr1 += gg[1][j] * w; xr2 += gg[2][j] * w;
        }
        float c1 = s_convw[d * DCONV + 1];
        float c2 = s_convw[d * DCONV + 2], c3 = s_convw[d * DCONV + 3];
        float cb = s_convb[d];
        float xc0 = silu_f(xr0 * c3 + cb);
        float xc1 = silu_f(xr0 * c2 + xr1 * c3 + cb);
        float xc2 = silu_f(xr0 * c1 + xr1 * c2 + xr2 * c3 + cb);
        xcr[0][i] = xc0; xcr[1][i] = xc1; xcr[2][i] = xc2;
#pragma unroll
        for (int r = 0; r < NDBC; r++) {
            float w = s_xproj[r * DINNER + d];
            dbc[0][r] += xc0 * w;
            dbc[1][r] += xc1 * w;
            dbc[2][r] += xc2 * w;
        }
    }
#pragma unroll
    for (int l = 0; l < 3; l++)
#pragma unroll
        for (int r = 0; r < NDBC; r++) dbc[l][r] = grp4_sum(dbc[l][r]);

    // ---- SSM over own 8 d-channels, partial o, then reduce --------------------
    float o[3][GD];
#pragma unroll
    for (int l = 0; l < 3; l++)
#pragma unroll
        for (int j = 0; j < GD; j++) o[l][j] = 0.f;

#pragma unroll
    for (int i = 0; i < 8; i++) {
        int d = k * 8 + i;
        float h[DSTATE];
#pragma unroll
        for (int s = 0; s < DSTATE; s++) h[s] = 0.f;

#pragma unroll
        for (int l = 0; l < 3; l++) {
            float dts = softplus_f(dbc[l][0] * s_dtw[d] + s_dtb[d]);
            float xld = xcr[l][i];
            float dtx = dts * xld;
            float yld = 0.f;
#pragma unroll
            for (int s = 0; s < DSTATE; s++) {
                h[s] = __expf(dts * s_A[d * DSTATE + s]) * h[s]
                     + dtx * dbc[l][1 + s];
                yld += h[s] * dbc[l][1 + DSTATE + s];
            }
            yld += s_D[d] * xld;
            float zld = 0.f;
#pragma unroll
            for (int j = 0; j < GD; j++)
                zld += gg[l][j] * s_inproj[(DINNER + d) * GD + j];
            yld *= silu_f(zld);
#pragma unroll
            for (int j = 0; j < GD; j++)
                o[l][j] += yld * s_outproj[j * DINNER + d];
        }
    }
#pragma unroll
    for (int l = 0; l < 3; l++)
#pragma unroll
        for (int j = 0; j < GD; j++) o[l][j] = grp4_sum(o[l][j]);

    // ---- residual + layernorm + logit + softmax (k==0 writes) ----------------
    if (k == 0) {
        float logit[3];
#pragma unroll
        for (int l = 0; l < 3; l++) {
            float y2[GD];
            float mu = 0.f;
#pragma unroll
            for (int j = 0; j < GD; j++) { y2[j] = o[l][j] + gg[l][j]; mu += y2[j]; }
            mu *= (1.f / GD);
            float var = 0.f;
#pragma unroll
            for (int j = 0; j < GD; j++) { float dlt = y2[j] - mu; var += dlt * dlt; }
            var *= (1.f / GD);
            float rstd = rsqrtf(var + 1e-12f);
            float lg = 0.f;
#pragma unroll
            for (int j = 0; j < GD; j++)
                lg += ((y2[j] - mu) * rstd * s_lng[j] + s_lnb[j]) * s_tlw[j];
            logit[l] = lg + s_tlb;
        }
        float mmax = fmaxf(logit[0], fmaxf(logit[1], logit[2]));
        float e0 = __expf((logit[0] - mmax) / TEMP);
        float e1 = __expf((logit[1] - mmax) / TEMP);
        float e2s = __expf((logit[2] - mmax) / TEMP);
        float inv = 1.f / (e0 + e1 + e2s);
        s_w[nl * 3 + 0] = e0 * inv;
        s_w[nl * 3 + 1] = e1 * inv;
        s_w[nl * 3 + 2] = e2s * inv;
    }
    __syncthreads();

    // ---- coalesced float4 output ----------------------------------------------
    const int base = blockIdx.x * NPB;
    for (int i = tid; i < NPB * 16; i += 128) {
        int n  = i >> 4;
        int c4 = (i & 15) * 4;
        int nn = s_nid[n];
        float w0 = s_w[n * 3 + 0], w1 = s_w[n * 3 + 1], w2 = s_w[n * 3 + 2];
        const float* r0 = (nn < N_USER) ? (user + (size_t)nn * D)
                                        : (item + (size_t)(nn - N_USER) * D);
        float4 v0 = *reinterpret_cast<const float4*>(r0 + c4);
        float4 v1 = *reinterpret_cast<const float4*>(g_embA + (size_t)nn * D + c4);
        float4 v2 = *reinterpret_cast<const float4*>(&s_embB[n * 64 + c4]);
        float4 ov;
        ov.x = w0 * v0.x + w1 * v1.x + w2 * v2.x;
        ov.y = w0 * v0.y + w1 * v1.y + w2 * v2.y;
        ov.z = w0 * v0.z + w1 * v1.z + w2 * v2.z;
        ov.w = w0 * v0.w + w1 * v1.w + w2 * v2.w;
        *reinterpret_cast<float4*>(out + (size_t)(base + n) * D + c4) = ov;
    }
}

// ---------------------------------------------------------------------------
// Launch
// ---------------------------------------------------------------------------
extern "C" void kernel_launch(void* const* d_in, const int* in_sizes, int n_in,
                              void* d_out, int out_size) {
    const float *user, *item, *eval_, *down_w, *in_proj_w, *conv_w, *conv_b,
                *x_proj_w, *dt_proj_w, *dt_proj_b, *A_log, *D_param,
                *out_proj_w, *ln_g, *ln_b, *tl_w, *tl_b;
    const int *erow, *ecol, *nids;

    if (in_sizes[3] == 1024) {
        user      = (const float*)d_in[0];
        item      = (const float*)d_in[1];
        eval_     = (const float*)d_in[2];
        down_w    = (const float*)d_in[3];
        in_proj_w = (const float*)d_in[4];
        conv_w    = (const float*)d_in[5];
        conv_b    = (const float*)d_in[6];
        x_proj_w  = (const float*)d_in[7];
        dt_proj_w = (const float*)d_in[8];
        dt_proj_b = (const float*)d_in[9];
        A_log     = (const float*)d_in[10];
        D_param   = (const float*)d_in[11];
        out_proj_w= (const float*)d_in[12];
        ln_g      = (const float*)d_in[13];
        ln_b      = (const float*)d_in[14];
        tl_w      = (const float*)d_in[15];
        tl_b      = (const float*)d_in[16];
        erow      = (const int*)d_in[17];
        ecol      = (const int*)d_in[18];
        nids      = (const int*)d_in[19];
    } else {
        user      = (const float*)d_in[0];
        item      = (const float*)d_in[1];
        erow      = (const int*)d_in[2];
        ecol      = (const int*)d_in[3];
        eval_     = (const float*)d_in[4];
        nids      = (const int*)d_in[5];
        down_w    = (const float*)d_in[6];
        in_proj_w = (const float*)d_in[7];
        conv_w    = (const float*)d_in[8];
        conv_b    = (const float*)d_in[9];
        x_proj_w  = (const float*)d_in[10];
        dt_proj_w = (const float*)d_in[11];
        dt_proj_b = (const float*)d_in[12];
        A_log     = (const float*)d_in[13];
        D_param   = (const float*)d_in[14];
        out_proj_w= (const float*)d_in[15];
        ln_g      = (const float*)d_in[16];
        ln_b      = (const float*)d_in[17];
        tl_w      = (const float*)d_in[18];
        tl_b      = (const float*)d_in[19];
    }

    init_kernel<<<(NTOT + 255) / 256, 256>>>();
    mark2_kernel<<<(BATCH + 255) / 256, 256>>>(nids);
    mark1_kernel<<<(NNZ / 4 + 255) / 256, 256>>>(erow, ecol);
    bucket_kernel<<<(NNZ / 4 + 255) / 256, 256>>>(erow, ecol, eval_);

    gather_norm1_kernel<<<GN_GRID, 256>>>(user, item);

    mamba_fuse_kernel<<<BATCH / NPB, 128>>>(
        user, item, nids, down_w, in_proj_w, conv_w, conv_b, x_proj_w,
        dt_proj_w, dt_proj_b, A_log, D_param, out_proj_w, ln_g, ln_b,
        tl_w, tl_b, (float*)d_out);
}

// round 12
// speedup vs baseline: 1.0006x; 1.0006x over previous
#include <cuda_runtime.h>
#include <cstdint>
#include <cstddef>

#define N_USER 100000
#define N_ITEM 150000
#define NTOT   250000
#define D      64
#define NNZ    1250000
#define BATCH  16384
#define GD     16
#define DSTATE 8
#define DCONV  4
#define DINNER 32
#define DTRANK 1
#define NDBC   (DTRANK + 2 * DSTATE)   // 17
#define TEMP   0.8f
#define CAP    64
#define NWORDS ((NTOT + 31) / 32)

// ---------------------------------------------------------------------------
// Device scratch (no cudaMalloc allowed)
// ---------------------------------------------------------------------------
__device__ float    g_embA[(size_t)NTOT * D];
__device__ int      g_cnt[NTOT];
__device__ float2   g_bucket[(size_t)NTOT * CAP];
__device__ unsigned g_need1[NWORDS];
__device__ unsigned g_need2[NWORDS];

__device__ __forceinline__ bool testbit(const unsigned* bm, int i) {
    return (bm[i >> 5] >> (i & 31)) & 1u;
}

// ---------------------------------------------------------------------------
// Init
// ---------------------------------------------------------------------------
__global__ void init_kernel() {
    int i = blockIdx.x * blockDim.x + threadIdx.x;
    if (i < NTOT)   g_cnt[i] = 0;
    if (i < NWORDS) { g_need1[i] = 0; g_need2[i] = 0; }
}

__global__ void mark2_kernel(const int* __restrict__ node_ids) {
    int i = blockIdx.x * blockDim.x + threadIdx.x;
    if (i >= BATCH) return;
    int nid = node_ids[i];
    atomicOr(&g_need2[nid >> 5], 1u << (nid & 31));
    atomicOr(&g_need1[nid >> 5], 1u << (nid & 31));
}

__global__ void mark1_kernel(const int* __restrict__ erow,
                             const int* __restrict__ ecol) {
    int i = blockIdx.x * blockDim.x + threadIdx.x;
    if (i >= NNZ / 4) return;
    int4 r = reinterpret_cast<const int4*>(erow)[i];
    int4 c = reinterpret_cast<const int4*>(ecol)[i];
    if (testbit(g_need2, r.x)) atomicOr(&g_need1[c.x >> 5], 1u << (c.x & 31));
    if (testbit(g_need2, r.y)) atomicOr(&g_need1[c.y >> 5], 1u << (c.y & 31));
    if (testbit(g_need2, r.z)) atomicOr(&g_need1[c.z >> 5], 1u << (c.z & 31));
    if (testbit(g_need2, r.w)) atomicOr(&g_need1[c.w >> 5], 1u << (c.w & 31));
}

// Bucket scatter (bitmap-filtered), 4 edges per thread.
__global__ void bucket_kernel(const int*   __restrict__ erow,
                              const int*   __restrict__ ecol,
                              const float* __restrict__ eval) {
    int i = blockIdx.x * blockDim.x + threadIdx.x;
    if (i >= NNZ / 4) return;
    int4   r = reinterpret_cast<const int4*>(erow)[i];
    int4   c = reinterpret_cast<const int4*>(ecol)[i];
    float4 v = reinterpret_cast<const float4*>(eval)[i];
    if (testbit(g_need1, r.x)) {
        int p = atomicAdd(&g_cnt[r.x], 1);
        if (p < CAP) g_bucket[(size_t)r.x * CAP + p] = make_float2(__int_as_float(c.x), v.x);
    }
    if (testbit(g_need1, r.y)) {
        int p = atomicAdd(&g_cnt[r.y], 1);
        if (p < CAP) g_bucket[(size_t)r.y * CAP + p] = make_float2(__int_as_float(c.y), v.y);
    }
    if (testbit(g_need1, r.z)) {
        int p = atomicAdd(&g_cnt[r.z], 1);
        if (p < CAP) g_bucket[(size_t)r.z * CAP + p] = make_float2(__int_as_float(c.z), v.z);
    }
    if (testbit(g_need1, r.w)) {
        int p = atomicAdd(&g_cnt[r.w], 1);
        if (p < CAP) g_bucket[(size_t)r.w * CAP + p] = make_float2(__int_as_float(c.w), v.w);
    }
}

// ---------------------------------------------------------------------------
// Layer-1 fused gather + L2-normalize (bitmap-gated, ROW-ORDERED — locality
// of bucket reads / embA writes matters; round-10 rowlist regression).
// 16 lanes per row; x4-unrolled edge loop, 4 accumulators, float4 edge loads.
// ---------------------------------------------------------------------------
__global__ __launch_bounds__(256)
void gather_norm1_kernel(const float* __restrict__ user,
                         const float* __restrict__ item) {
    unsigned t = blockIdx.x * blockDim.x + threadIdx.x;
    unsigned r = t >> 4;
    if (r >= NTOT) return;
    if (!testbit(g_need1, (int)r)) return;
    unsigned q = (t & 15u) * 4u;

    int deg = g_cnt[r]; if (deg > CAP) deg = CAP;
    const float2* eb  = g_bucket + (size_t)r * CAP;
    const float4* eb4 = reinterpret_cast<const float4*>(eb);

    float4 a0 = make_float4(0.f, 0.f, 0.f, 0.f);
    float4 a1 = make_float4(0.f, 0.f, 0.f, 0.f);
    float4 a2 = make_float4(0.f, 0.f, 0.f, 0.f);
    float4 a3 = make_float4(0.f, 0.f, 0.f, 0.f);
    int p = 0;
    for (; p + 3 < deg; p += 4) {
        float4 e01 = eb4[p >> 1];
        float4 e23 = eb4[(p >> 1) + 1];
        int c0 = __float_as_int(e01.x), c1 = __float_as_int(e01.z);
        int c2 = __float_as_int(e23.x), c3 = __float_as_int(e23.z);
        const float* s0 = (c0 < N_USER) ? (user + (size_t)c0 * D)
                                        : (item + (size_t)(c0 - N_USER) * D);
        const float* s1 = (c1 < N_USER) ? (user + (size_t)c1 * D)
                                        : (item + (size_t)(c1 - N_USER) * D);
        const float* s2 = (c2 < N_USER) ? (user + (size_t)c2 * D)
                                        : (item + (size_t)(c2 - N_USER) * D);
        const float* s3 = (c3 < N_USER) ? (user + (size_t)c3 * D)
                                        : (item + (size_t)(c3 - N_USER) * D);
        float4 v0 = *reinterpret_cast<const float4*>(s0 + q);
        float4 v1 = *reinterpret_cast<const float4*>(s1 + q);
        float4 v2 = *reinterpret_cast<const float4*>(s2 + q);
        float4 v3 = *reinterpret_cast<const float4*>(s3 + q);
        a0.x += e01.y * v0.x; a0.y += e01.y * v0.y; a0.z += e01.y * v0.z; a0.w += e01.y * v0.w;
        a1.x += e01.w * v1.x; a1.y += e01.w * v1.y; a1.z += e01.w * v1.z; a1.w += e01.w * v1.w;
        a2.x += e23.y * v2.x; a2.y += e23.y * v2.y; a2.z += e23.y * v2.z; a2.w += e23.y * v2.w;
        a3.x += e23.w * v3.x; a3.y += e23.w * v3.y; a3.z += e23.w * v3.z; a3.w += e23.w * v3.w;
    }
    for (; p < deg; p++) {
        float2 e = eb[p];
        int c = __float_as_int(e.x);
        const float* sp = (c < N_USER) ? (user + (size_t)c * D)
                                       : (item + (size_t)(c - N_USER) * D);
        float4 s = *reinterpret_cast<const float4*>(sp + q);
        a0.x += e.y * s.x; a0.y += e.y * s.y; a0.z += e.y * s.z; a0.w += e.y * s.w;
    }
    float4 acc = make_float4(a0.x + a1.x + a2.x + a3.x,
                             a0.y + a1.y + a2.y + a3.y,
                             a0.z + a1.z + a2.z + a3.z,
                             a0.w + a1.w + a2.w + a3.w);

    float ss = acc.x * acc.x + acc.y * acc.y + acc.z * acc.z + acc.w * acc.w;
#pragma unroll
    for (int o = 8; o > 0; o >>= 1)
        ss += __shfl_xor_sync(0xffffffffu, ss, o, 16);
    float inv = 1.0f / fmaxf(sqrtf(ss), 1e-12f);
    acc.x *= inv; acc.y *= inv; acc.z *= inv; acc.w *= inv;

    *reinterpret_cast<float4*>(g_embA + (size_t)r * D + q) = acc;
}

// ---------------------------------------------------------------------------
// Fused layer-2 gather + Mamba + LayerNorm + softmax fusion (4 threads/node).
// ---------------------------------------------------------------------------
__device__ __forceinline__ float softplus_f(float x) {
    return (x > 20.f) ? x : log1pf(__expf(x));
}
__device__ __forceinline__ float silu_f(float x) {
    return x / (1.f + __expf(-x));
}
__device__ __forceinline__ float grp4_sum(float x) {
    x += __shfl_xor_sync(0xffffffffu, x, 1);
    x += __shfl_xor_sync(0xffffffffu, x, 2);
    return x;
}

#define NPB 32   // nodes per block

__global__ __launch_bounds__(128)
void mamba_fuse_kernel(const float* __restrict__ user,
                       const float* __restrict__ item,
                       const int*   __restrict__ node_ids,
                       const float* __restrict__ down_w,
                       const float* __restrict__ in_proj_w,
                       const float* __restrict__ conv_w,
                       const float* __restrict__ conv_b,
                       const float* __restrict__ x_proj_w,
                       const float* __restrict__ dt_proj_w,
                       const float* __restrict__ dt_proj_b,
                       const float* __restrict__ A_log,
                       const float* __restrict__ D_param,
                       const float* __restrict__ out_proj_w,
                       const float* __restrict__ ln_g,
                       const float* __restrict__ ln_b,
                       const float* __restrict__ to_logit_w,
                       const float* __restrict__ to_logit_b,
                       float* __restrict__ out) {
    __shared__ __align__(16) float s_embB[NPB * 64];
    __shared__ float s_down[GD * 64];
    __shared__ float s_inproj[2 * DINNER * GD];
    __shared__ float s_convw[DINNER * DCONV];
    __shared__ float s_convb[DINNER];
    __shared__ float s_xproj[NDBC * DINNER];
    __shared__ float s_dtw[DINNER];
    __shared__ float s_dtb[DINNER];
    __shared__ float s_A[DINNER * DSTATE];
    __shared__ float s_D[DINNER];
    __shared__ float s_outproj[GD * DINNER];
    __shared__ float s_lng[GD], s_lnb[GD], s_tlw[GD];
    __shared__ float s_tlb;
    __shared__ float s_w[NPB * 3];
    __shared__ int   s_nid[NPB];

    const int tid = threadIdx.x;
    for (int i = tid; i < GD * 64; i += 128)            s_down[i]   = down_w[i];
    for (int i = tid; i < 2 * DINNER * GD; i += 128)    s_inproj[i] = in_proj_w[i];
    for (int i = tid; i < DINNER * DCONV; i += 128)     s_convw[i]  = conv_w[i];
    for (int i = tid; i < NDBC * DINNER; i += 128)      s_xproj[i]  = x_proj_w[i];
    for (int i = tid; i < DINNER * DSTATE; i += 128)    s_A[i]      = -__expf(A_log[i]);
    for (int i = tid; i < GD * DINNER; i += 128)        s_outproj[i]= out_proj_w[i];
    if (tid < DINNER) {
        s_convb[tid] = conv_b[tid];
        s_dtw[tid]   = dt_proj_w[tid];
        s_dtb[tid]   = dt_proj_b[tid];
        s_D[tid]     = D_param[tid];
    }
    if (tid < GD) {
        s_lng[tid] = ln_g[tid];
        s_lnb[tid] = ln_b[tid];
        s_tlw[tid] = to_logit_w[tid];
    }
    if (tid == 0) s_tlb = to_logit_b[0];
    __syncthreads();

    const int nl  = tid >> 2;
    const int k   = tid & 3;
    const int b   = blockIdx.x * NPB + nl;
    const int nid = node_ids[b];
    if (k == 0) s_nid[nl] = nid;

    // ---- fused layer-2 gather: embB quarter (16 cols) -> shared -------------
    {
        float4 e2[4];
#pragma unroll
        for (int u = 0; u < 4; u++) e2[u] = make_float4(0.f, 0.f, 0.f, 0.f);
        int deg = g_cnt[nid]; if (deg > CAP) deg = CAP;
        const float2* eb = g_bucket + (size_t)nid * CAP;
        for (int p = 0; p < deg; p++) {
            float2 e = eb[p];
            int   c = __float_as_int(e.x);
            float v = e.y;
            const float4* src = reinterpret_cast<const float4*>(
                g_embA + (size_t)c * D + k * 16);
#pragma unroll
            for (int u = 0; u < 4; u++) {
                float4 s = src[u];
                e2[u].x += v * s.x; e2[u].y += v * s.y;
                e2[u].z += v * s.z; e2[u].w += v * s.w;
            }
        }
        float ss = 0.f;
#pragma unroll
        for (int u = 0; u < 4; u++)
            ss += e2[u].x * e2[u].x + e2[u].y * e2[u].y
                + e2[u].z * e2[u].z + e2[u].w * e2[u].w;
        ss = grp4_sum(ss);
        float inv = 1.0f / fmaxf(sqrtf(ss), 1e-12f);
#pragma unroll
        for (int u = 0; u < 4; u++) {
            e2[u].x *= inv; e2[u].y *= inv; e2[u].z *= inv; e2[u].w *= inv;
            *reinterpret_cast<float4*>(&s_embB[nl * 64 + k * 16 + u * 4]) = e2[u];
        }
    }
    __syncwarp();

    // ---- g = seq @ down_w.T --------------------------------------------------
    float gg[3][GD];
#pragma unroll
    for (int l = 0; l < 3; l++)
#pragma unroll
        for (int j = 0; j < GD; j++) gg[l][j] = 0.f;

#pragma unroll
    for (int l = 0; l < 3; l++) {
        float4 rq[4];
        if (l == 2) {
#pragma unroll
            for (int u = 0; u < 4; u++)
                rq[u] = *reinterpret_cast<const float4*>(&s_embB[nl * 64 + k * 16 + u * 4]);
        } else {
            const float* row;
            if (l == 0)
                row = (nid < N_USER) ? (user + (size_t)nid * D)
                                     : (item + (size_t)(nid - N_USER) * D);
            else
                row = g_embA + (size_t)nid * D;
            const float4* r4 = reinterpret_cast<const float4*>(row + k * 16);
#pragma unroll
            for (int u = 0; u < 4; u++) rq[u] = r4[u];
        }
#pragma unroll
        for (int u = 0; u < 4; u++) {
            float4 sv = rq[u];
            int colbase = k * 16 + u * 4;
#pragma unroll
            for (int j = 0; j < GD; j++) {
                const float* dwj = &s_down[j * 64 + colbase];
                gg[l][j] += sv.x * dwj[0] + sv.y * dwj[1]
                          + sv.z * dwj[2] + sv.w * dwj[3];
            }
        }
    }
#pragma unroll
    for (int l = 0; l < 3; l++)
#pragma unroll
        for (int j = 0; j < GD; j++) gg[l][j] = grp4_sum(gg[l][j]);

    // ---- dbc over own 8 d-channels (xc cached), then reduce -------------------
    float dbc[3][NDBC];
    float xcr[3][8];
#pragma unroll
    for (int l = 0; l < 3; l++)
#pragma unroll
        for (int r = 0; r < NDBC; r++) dbc[l][r] = 0.f;

#pragma unroll
    for (int i = 0; i < 8; i++) {
        int d = k * 8 + i;
        float xr0 = 0.f, xr1 = 0.f, xr2 = 0.f;
#pragma unroll
        for (int j = 0; j < GD; j++) {
            float w = s_inproj[d * GD + j];
            xr0 += gg[0][j] * w; xr1 += gg[1][j] * w; xr2 += gg[2][j] * w;
        }
        float c1 = s_convw[d * DCONV + 1];
        float c2 = s_convw[d * DCONV + 2], c3 = s_convw[d * DCONV + 3];
        float cb = s_convb[d];
        float xc0 = silu_f(xr0 * c3 + cb);
        float xc1 = silu_f(xr0 * c2 + xr1 * c3 + cb);
        float xc2 = silu_f(xr0 * c1 + xr1 * c2 + xr2 * c3 + cb);
        xcr[0][i] = xc0; xcr[1][i] = xc1; xcr[2][i] = xc2;
#pragma unroll
        for (int r = 0; r < NDBC; r++) {
            float w = s_xproj[r * DINNER + d];
            dbc[0][r] += xc0 * w;
            dbc[1][r] += xc1 * w;
            dbc[2][r] += xc2 * w;
        }
    }
#pragma unroll
    for (int l = 0; l < 3; l++)
#pragma unroll
        for (int r = 0; r < NDBC; r++) dbc[l][r] = grp4_sum(dbc[l][r]);

    // ---- SSM over own 8 d-channels, partial o, then reduce --------------------
    float o[3][GD];
#pragma unroll
    for (int l = 0; l < 3; l++)
#pragma unroll
        for (int j = 0; j < GD; j++) o[l][j] = 0.f;

#pragma unroll
    for (int i = 0; i < 8; i++) {
        int d = k * 8 + i;
        float h[DSTATE];
#pragma unroll
        for (int s = 0; s < DSTATE; s++) h[s] = 0.f;

#pragma unroll
        for (int l = 0; l < 3; l++) {
            float dts = softplus_f(dbc[l][0] * s_dtw[d] + s_dtb[d]);
            float xld = xcr[l][i];
            float dtx = dts * xld;
            float yld = 0.f;
#pragma unroll
            for (int s = 0; s < DSTATE; s++) {
                h[s] = __expf(dts * s_A[d * DSTATE + s]) * h[s]
                     + dtx * dbc[l][1 + s];
                yld += h[s] * dbc[l][1 + DSTATE + s];
            }
            yld += s_D[d] * xld;
            float zld = 0.f;
#pragma unroll
            for (int j = 0; j < GD; j++)
                zld += gg[l][j] * s_inproj[(DINNER + d) * GD + j];
            yld *= silu_f(zld);
#pragma unroll
            for (int j = 0; j < GD; j++)
                o[l][j] += yld * s_outproj[j * DINNER + d];
        }
    }
#pragma unroll
    for (int l = 0; l < 3; l++)
#pragma unroll
        for (int j = 0; j < GD; j++) o[l][j] = grp4_sum(o[l][j]);

    // ---- residual + layernorm + logit + softmax (k==0 writes) ----------------
    if (k == 0) {
        float logit[3];
#pragma unroll
        for (int l = 0; l < 3; l++) {
            float y2[GD];
            float mu = 0.f;
#pragma unroll
            for (int j = 0; j < GD; j++) { y2[j] = o[l][j] + gg[l][j]; mu += y2[j]; }
            mu *= (1.f / GD);
            float var = 0.f;
#pragma unroll
            for (int j = 0; j < GD; j++) { float dlt = y2[j] - mu; var += dlt * dlt; }
            var *= (1.f / GD);
            float rstd = rsqrtf(var + 1e-12f);
            float lg = 0.f;
#pragma unroll
            for (int j = 0; j < GD; j++)
                lg += ((y2[j] - mu) * rstd * s_lng[j] + s_lnb[j]) * s_tlw[j];
            logit[l] = lg + s_tlb;
        }
        float mmax = fmaxf(logit[0], fmaxf(logit[1], logit[2]));
        float e0 = __expf((logit[0] - mmax) / TEMP);
        float e1 = __expf((logit[1] - mmax) / TEMP);
        float e2s = __expf((logit[2] - mmax) / TEMP);
        float inv = 1.f / (e0 + e1 + e2s);
        s_w[nl * 3 + 0] = e0 * inv;
        s_w[nl * 3 + 1] = e1 * inv;
        s_w[nl * 3 + 2] = e2s * inv;
    }
    __syncthreads();

    // ---- coalesced float4 output ----------------------------------------------
    const int base = blockIdx.x * NPB;
    for (int i = tid; i < NPB * 16; i += 128) {
        int n  = i >> 4;
        int c4 = (i & 15) * 4;
        int nn = s_nid[n];
        float w0 = s_w[n * 3 + 0], w1 = s_w[n * 3 + 1], w2 = s_w[n * 3 + 2];
        const float* r0 = (nn < N_USER) ? (user + (size_t)nn * D)
                                        : (item + (size_t)(nn - N_USER) * D);
        float4 v0 = *reinterpret_cast<const float4*>(r0 + c4);
        float4 v1 = *reinterpret_cast<const float4*>(g_embA + (size_t)nn * D + c4);
        float4 v2 = *reinterpret_cast<const float4*>(&s_embB[n * 64 + c4]);
        float4 ov;
        ov.x = w0 * v0.x + w1 * v1.x + w2 * v2.x;
        ov.y = w0 * v0.y + w1 * v1.y + w2 * v2.y;
        ov.z = w0 * v0.z + w1 * v1.z + w2 * v2.z;
        ov.w = w0 * v0.w + w1 * v1.w + w2 * v2.w;
        *reinterpret_cast<float4*>(out + (size_t)(base + n) * D + c4) = ov;
    }
}

// ---------------------------------------------------------------------------
// Launch
// ---------------------------------------------------------------------------
extern "C" void kernel_launch(void* const* d_in, const int* in_sizes, int n_in,
                              void* d_out, int out_size) {
    const float *user, *item, *eval_, *down_w, *in_proj_w, *conv_w, *conv_b,
                *x_proj_w, *dt_proj_w, *dt_proj_b, *A_log, *D_param,
                *out_proj_w, *ln_g, *ln_b, *tl_w, *tl_b;
    const int *erow, *ecol, *nids;

    if (in_sizes[3] == 1024) {
        user      = (const float*)d_in[0];
        item      = (const float*)d_in[1];
        eval_     = (const float*)d_in[2];
        down_w    = (const float*)d_in[3];
        in_proj_w = (const float*)d_in[4];
        conv_w    = (const float*)d_in[5];
        conv_b    = (const float*)d_in[6];
        x_proj_w  = (const float*)d_in[7];
        dt_proj_w = (const float*)d_in[8];
        dt_proj_b = (const float*)d_in[9];
        A_log     = (const float*)d_in[10];
        D_param   = (const float*)d_in[11];
        out_proj_w= (const float*)d_in[12];
        ln_g      = (const float*)d_in[13];
        ln_b      = (const float*)d_in[14];
        tl_w      = (const float*)d_in[15];
        tl_b      = (const float*)d_in[16];
        erow      = (const int*)d_in[17];
        ecol      = (const int*)d_in[18];
        nids      = (const int*)d_in[19];
    } else {
        user      = (const float*)d_in[0];
        item      = (const float*)d_in[1];
        erow      = (const int*)d_in[2];
        ecol      = (const int*)d_in[3];
        eval_     = (const float*)d_in[4];
        nids      = (const int*)d_in[5];
        down_w    = (const float*)d_in[6];
        in_proj_w = (const float*)d_in[7];
        conv_w    = (const float*)d_in[8];
        conv_b    = (const float*)d_in[9];
        x_proj_w  = (const float*)d_in[10];
        dt_proj_w = (const float*)d_in[11];
        dt_proj_b = (const float*)d_in[12];
        A_log     = (const float*)d_in[13];
        D_param   = (const float*)d_in[14];
        out_proj_w= (const float*)d_in[15];
        ln_g      = (const float*)d_in[16];
        ln_b      = (const float*)d_in[17];
        tl_w      = (const float*)d_in[18];
        tl_b      = (const float*)d_in[19];
    }

    init_kernel<<<(NTOT + 255) / 256, 256>>>();
    mark2_kernel<<<(BATCH + 255) / 256, 256>>>(nids);
    mark1_kernel<<<(NNZ / 4 + 255) / 256, 256>>>(erow, ecol);
    bucket_kernel<<<(NNZ / 4 + 255) / 256, 256>>>(erow, ecol, eval_);

    const int gn_blocks = (NTOT * 16 + 255) / 256;
    gather_norm1_kernel<<<gn_blocks, 256>>>(user, item);

    mamba_fuse_kernel<<<BATCH / NPB, 128>>>(
        user, item, nids, down_w, in_proj_w, conv_w, conv_b, x_proj_w,
        dt_proj_w, dt_proj_b, A_log, D_param, out_proj_w, ln_g, ln_b,
        tl_w, tl_b, (float*)d_out);
}

// round 15
// speedup vs baseline: 1.1355x; 1.1348x over previous
#include <cuda_runtime.h>
#include <cstdint>
#include <cstddef>

#define N_USER 100000
#define N_ITEM 150000
#define NTOT   250000
#define D      64
#define NNZ    1250000
#define BATCH  16384
#define GD     16
#define DSTATE 8
#define DCONV  4
#define DINNER 32
#define DTRANK 1
#define NDBC   (DTRANK + 2 * DSTATE)   // 17
#define TEMP   0.8f
#define CAP    64
#define NWORDS ((NTOT + 31) / 32)

// ---------------------------------------------------------------------------
// Device scratch (no cudaMalloc allowed). Zero-initialized at module load;
// cleanup_kernel (last launch) re-zeroes after every execution so each graph
// replay sees pristine state.
// ---------------------------------------------------------------------------
__device__ float    g_embA[(size_t)NTOT * D];
__device__ int      g_cnt[NTOT];
__device__ float2   g_bucket[(size_t)NTOT * CAP];
__device__ unsigned g_need1[NWORDS];
__device__ unsigned g_need2[NWORDS];

__device__ __forceinline__ bool testbit(const unsigned* bm, int i) {
    return (bm[i >> 5] >> (i & 31)) & 1u;
}

__global__ void mark2_kernel(const int* __restrict__ node_ids) {
    int i = blockIdx.x * blockDim.x + threadIdx.x;
    if (i >= BATCH) return;
    int nid = node_ids[i];
    atomicOr(&g_need2[nid >> 5], 1u << (nid & 31));
    atomicOr(&g_need1[nid >> 5], 1u << (nid & 31));
}

__global__ void mark1_kernel(const int* __restrict__ erow,
                             const int* __restrict__ ecol) {
    int i = blockIdx.x * blockDim.x + threadIdx.x;
    if (i >= NNZ / 4) return;
    int4 r = reinterpret_cast<const int4*>(erow)[i];
    int4 c = reinterpret_cast<const int4*>(ecol)[i];
    if (testbit(g_need2, r.x)) atomicOr(&g_need1[c.x >> 5], 1u << (c.x & 31));
    if (testbit(g_need2, r.y)) atomicOr(&g_need1[c.y >> 5], 1u << (c.y & 31));
    if (testbit(g_need2, r.z)) atomicOr(&g_need1[c.z >> 5], 1u << (c.z & 31));
    if (testbit(g_need2, r.w)) atomicOr(&g_need1[c.w >> 5], 1u << (c.w & 31));
}

// Bucket scatter (bitmap-filtered), 4 edges per thread.
__global__ void bucket_kernel(const int*   __restrict__ erow,
                              const int*   __restrict__ ecol,
                              const float* __restrict__ eval) {
    int i = blockIdx.x * blockDim.x + threadIdx.x;
    if (i >= NNZ / 4) return;
    int4   r = reinterpret_cast<const int4*>(erow)[i];
    int4   c = reinterpret_cast<const int4*>(ecol)[i];
    float4 v = reinterpret_cast<const float4*>(eval)[i];
    if (testbit(g_need1, r.x)) {
        int p = atomicAdd(&g_cnt[r.x], 1);
        if (p < CAP) g_bucket[(size_t)r.x * CAP + p] = make_float2(__int_as_float(c.x), v.x);
    }
    if (testbit(g_need1, r.y)) {
        int p = atomicAdd(&g_cnt[r.y], 1);
        if (p < CAP) g_bucket[(size_t)r.y * CAP + p] = make_float2(__int_as_float(c.y), v.y);
    }
    if (testbit(g_need1, r.z)) {
        int p = atomicAdd(&g_cnt[r.z], 1);
        if (p < CAP) g_bucket[(size_t)r.z * CAP + p] = make_float2(__int_as_float(c.z), v.z);
    }
    if (testbit(g_need1, r.w)) {
        int p = atomicAdd(&g_cnt[r.w], 1);
        if (p < CAP) g_bucket[(size_t)r.w * CAP + p] = make_float2(__int_as_float(c.w), v.w);
    }
}

// ---------------------------------------------------------------------------
// Layer-1 fused gather + L2-normalize (bitmap-gated, row-ordered).
// ROUND-9 FORM EXACTLY: 16 lanes/row, x2-unrolled edge loop, dual
// accumulators, float2 edge loads — empirically the fastest variant
// (x4/float4 regressed 20us via occupancy loss; rowlist regressed locality).
// ---------------------------------------------------------------------------
__global__ __launch_bounds__(256)
void gather_norm1_kernel(const float* __restrict__ user,
                         const float* __restrict__ item) {
    unsigned t = blockIdx.x * blockDim.x + threadIdx.x;
    unsigned r = t >> 4;
    if (r >= NTOT) return;
    if (!testbit(g_need1, (int)r)) return;
    unsigned q = (t & 15u) * 4u;

    int deg = g_cnt[r]; if (deg > CAP) deg = CAP;
    const float2* eb = g_bucket + (size_t)r * CAP;

    float4 acc0 = make_float4(0.f, 0.f, 0.f, 0.f);
    float4 acc1 = make_float4(0.f, 0.f, 0.f, 0.f);
    int p = 0;
    for (; p + 1 < deg; p += 2) {
        float2 e0 = eb[p];
        float2 e1 = eb[p + 1];
        int c0 = __float_as_int(e0.x);
        int c1 = __float_as_int(e1.x);
        const float* sp0 = (c0 < N_USER) ? (user + (size_t)c0 * D)
                                         : (item + (size_t)(c0 - N_USER) * D);
        const float* sp1 = (c1 < N_USER) ? (user + (size_t)c1 * D)
                                         : (item + (size_t)(c1 - N_USER) * D);
        float4 s0 = *reinterpret_cast<const float4*>(sp0 + q);
        float4 s1 = *reinterpret_cast<const float4*>(sp1 + q);
        acc0.x += e0.y * s0.x; acc0.y += e0.y * s0.y;
        acc0.z += e0.y * s0.z; acc0.w += e0.y * s0.w;
        acc1.x += e1.y * s1.x; acc1.y += e1.y * s1.y;
        acc1.z += e1.y * s1.z; acc1.w += e1.y * s1.w;
    }
    if (p < deg) {
        float2 e = eb[p];
        int c = __float_as_int(e.x);
        const float* sp = (c < N_USER) ? (user + (size_t)c * D)
                                       : (item + (size_t)(c - N_USER) * D);
        float4 s = *reinterpret_cast<const float4*>(sp + q);
        acc0.x += e.y * s.x; acc0.y += e.y * s.y;
        acc0.z += e.y * s.z; acc0.w += e.y * s.w;
    }
    float4 acc = make_float4(acc0.x + acc1.x, acc0.y + acc1.y,
                             acc0.z + acc1.z, acc0.w + acc1.w);

    float ss = acc.x * acc.x + acc.y * acc.y + acc.z * acc.z + acc.w * acc.w;
#pragma unroll
    for (int o = 8; o > 0; o >>= 1)
        ss += __shfl_xor_sync(0xffffffffu, ss, o, 16);
    float inv = 1.0f / fmaxf(sqrtf(ss), 1e-12f);
    acc.x *= inv; acc.y *= inv; acc.z *= inv; acc.w *= inv;

    *reinterpret_cast<float4*>(g_embA + (size_t)r * D + q) = acc;
}

// ---------------------------------------------------------------------------
// Fused layer-2 gather + Mamba + LayerNorm + softmax fusion (4 threads/node).
// Layer-2 gather now x2-unrolled with a second accumulator set.
// ---------------------------------------------------------------------------
__device__ __forceinline__ float softplus_f(float x) {
    return (x > 20.f) ? x : log1pf(__expf(x));
}
__device__ __forceinline__ float silu_f(float x) {
    return x / (1.f + __expf(-x));
}
__device__ __forceinline__ float grp4_sum(float x) {
    x += __shfl_xor_sync(0xffffffffu, x, 1);
    x += __shfl_xor_sync(0xffffffffu, x, 2);
    return x;
}

#define NPB 32   // nodes per block

__global__ __launch_bounds__(128)
void mamba_fuse_kernel(const float* __restrict__ user,
                       const float* __restrict__ item,
                       const int*   __restrict__ node_ids,
                       const float* __restrict__ down_w,
                       const float* __restrict__ in_proj_w,
                       const float* __restrict__ conv_w,
                       const float* __restrict__ conv_b,
                       const float* __restrict__ x_proj_w,
                       const float* __restrict__ dt_proj_w,
                       const float* __restrict__ dt_proj_b,
                       const float* __restrict__ A_log,
                       const float* __restrict__ D_param,
                       const float* __restrict__ out_proj_w,
                       const float* __restrict__ ln_g,
                       const float* __restrict__ ln_b,
                       const float* __restrict__ to_logit_w,
                       const float* __restrict__ to_logit_b,
                       float* __restrict__ out) {
    __shared__ __align__(16) float s_embB[NPB * 64];
    __shared__ float s_down[GD * 64];
    __shared__ float s_inproj[2 * DINNER * GD];
    __shared__ float s_convw[DINNER * DCONV];
    __shared__ float s_convb[DINNER];
    __shared__ float s_xproj[NDBC * DINNER];
    __shared__ float s_dtw[DINNER];
    __shared__ float s_dtb[DINNER];
    __shared__ float s_A[DINNER * DSTATE];
    __shared__ float s_D[DINNER];
    __shared__ float s_outproj[GD * DINNER];
    __shared__ float s_lng[GD], s_lnb[GD], s_tlw[GD];
    __shared__ float s_tlb;
    __shared__ float s_w[NPB * 3];
    __shared__ int   s_nid[NPB];

    const int tid = threadIdx.x;
    for (int i = tid; i < GD * 64; i += 128)            s_down[i]   = down_w[i];
    for (int i = tid; i < 2 * DINNER * GD; i += 128)    s_inproj[i] = in_proj_w[i];
    for (int i = tid; i < DINNER * DCONV; i += 128)     s_convw[i]  = conv_w[i];
    for (int i = tid; i < NDBC * DINNER; i += 128)      s_xproj[i]  = x_proj_w[i];
    for (int i = tid; i < DINNER * DSTATE; i += 128)    s_A[i]      = -__expf(A_log[i]);
    for (int i = tid; i < GD * DINNER; i += 128)        s_outproj[i]= out_proj_w[i];
    if (tid < DINNER) {
        s_convb[tid] = conv_b[tid];
        s_dtw[tid]   = dt_proj_w[tid];
        s_dtb[tid]   = dt_proj_b[tid];
        s_D[tid]     = D_param[tid];
    }
    if (tid < GD) {
        s_lng[tid] = ln_g[tid];
        s_lnb[tid] = ln_b[tid];
        s_tlw[tid] = to_logit_w[tid];
    }
    if (tid == 0) s_tlb = to_logit_b[0];
    __syncthreads();

    const int nl  = tid >> 2;
    const int k   = tid & 3;
    const int b   = blockIdx.x * NPB + nl;
    const int nid = node_ids[b];
    if (k == 0) s_nid[nl] = nid;

    // ---- fused layer-2 gather: embB quarter (16 cols) -> shared -------------
    // x2-unrolled: two independent accumulator sets double in-flight loads.
    {
        float4 e2[4], f2[4];
#pragma unroll
        for (int u = 0; u < 4; u++) {
            e2[u] = make_float4(0.f, 0.f, 0.f, 0.f);
            f2[u] = make_float4(0.f, 0.f, 0.f, 0.f);
        }
        int deg = g_cnt[nid]; if (deg > CAP) deg = CAP;
        const float2* eb = g_bucket + (size_t)nid * CAP;
        int p = 0;
        for (; p + 1 < deg; p += 2) {
            float2 ea = eb[p];
            float2 ebb = eb[p + 1];
            int   ca = __float_as_int(ea.x);
            int   cb = __float_as_int(ebb.x);
            const float4* sa = reinterpret_cast<const float4*>(
                g_embA + (size_t)ca * D + k * 16);
            const float4* sb = reinterpret_cast<const float4*>(
                g_embA + (size_t)cb * D + k * 16);
#pragma unroll
            for (int u = 0; u < 4; u++) {
                float4 va = sa[u];
                float4 vb = sb[u];
                e2[u].x += ea.y * va.x; e2[u].y += ea.y * va.y;
                e2[u].z += ea.y * va.z; e2[u].w += ea.y * va.w;
                f2[u].x += ebb.y * vb.x; f2[u].y += ebb.y * vb.y;
                f2[u].z += ebb.y * vb.z; f2[u].w += ebb.y * vb.w;
            }
        }
        if (p < deg) {
            float2 e = eb[p];
            int   c = __float_as_int(e.x);
            const float4* src = reinterpret_cast<const float4*>(
                g_embA + (size_t)c * D + k * 16);
#pragma unroll
            for (int u = 0; u < 4; u++) {
                float4 s = src[u];
                e2[u].x += e.y * s.x; e2[u].y += e.y * s.y;
                e2[u].z += e.y * s.z; e2[u].w += e.y * s.w;
            }
        }
#pragma unroll
        for (int u = 0; u < 4; u++) {
            e2[u].x += f2[u].x; e2[u].y += f2[u].y;
            e2[u].z += f2[u].z; e2[u].w += f2[u].w;
        }
        float ss = 0.f;
#pragma unroll
        for (int u = 0; u < 4; u++)
            ss += e2[u].x * e2[u].x + e2[u].y * e2[u].y
                + e2[u].z * e2[u].z + e2[u].w * e2[u].w;
        ss = grp4_sum(ss);
        float inv = 1.0f / fmaxf(sqrtf(ss), 1e-12f);
#pragma unroll
        for (int u = 0; u < 4; u++) {
            e2[u].x *= inv; e2[u].y *= inv; e2[u].z *= inv; e2[u].w *= inv;
            *reinterpret_cast<float4*>(&s_embB[nl * 64 + k * 16 + u * 4]) = e2[u];
        }
    }
    __syncwarp();

    // ---- g = seq @ down_w.T --------------------------------------------------
    float gg[3][GD];
#pragma unroll
    for (int l = 0; l < 3; l++)
#pragma unroll
        for (int j = 0; j < GD; j++) gg[l][j] = 0.f;

#pragma unroll
    for (int l = 0; l < 3; l++) {
        float4 rq[4];
        if (l == 2) {
#pragma unroll
            for (int u = 0; u < 4; u++)
                rq[u] = *reinterpret_cast<const float4*>(&s_embB[nl * 64 + k * 16 + u * 4]);
        } else {
            const float* row;
            if (l == 0)
                row = (nid < N_USER) ? (user + (size_t)nid * D)
                                     : (item + (size_t)(nid - N_USER) * D);
            else
                row = g_embA + (size_t)nid * D;
            const float4* r4 = reinterpret_cast<const float4*>(row + k * 16);
#pragma unroll
            for (int u = 0; u < 4; u++) rq[u] = r4[u];
        }
#pragma unroll
        for (int u = 0; u < 4; u++) {
            float4 sv = rq[u];
            int colbase = k * 16 + u * 4;
#pragma unroll
            for (int j = 0; j < GD; j++) {
                const float* dwj = &s_down[j * 64 + colbase];
                gg[l][j] += sv.x * dwj[0] + sv.y * dwj[1]
                          + sv.z * dwj[2] + sv.w * dwj[3];
            }
        }
    }
#pragma unroll
    for (int l = 0; l < 3; l++)
#pragma unroll
        for (int j = 0; j < GD; j++) gg[l][j] = grp4_sum(gg[l][j]);

    // ---- dbc over own 8 d-channels (xc cached), then reduce -------------------
    float dbc[3][NDBC];
    float xcr[3][8];
#pragma unroll
    for (int l = 0; l < 3; l++)
#pragma unroll
        for (int r = 0; r < NDBC; r++) dbc[l][r] = 0.f;

#pragma unroll
    for (int i = 0; i < 8; i++) {
        int d = k * 8 + i;
        float xr0 = 0.f, xr1 = 0.f, xr2 = 0.f;
#pragma unroll
        for (int j = 0; j < GD; j++) {
            float w = s_inproj[d * GD + j];
            xr0 += gg[0][j] * w; xr1 += gg[1][j] * w; xr2 += gg[2][j] * w;
        }
        float c1 = s_convw[d * DCONV + 1];
        float c2 = s_convw[d * DCONV + 2], c3 = s_convw[d * DCONV + 3];
        float cb = s_convb[d];
        float xc0 = silu_f(xr0 * c3 + cb);
        float xc1 = silu_f(xr0 * c2 + xr1 * c3 + cb);
        float xc2 = silu_f(xr0 * c1 + xr1 * c2 + xr2 * c3 + cb);
        xcr[0][i] = xc0; xcr[1][i] = xc1; xcr[2][i] = xc2;
#pragma unroll
        for (int r = 0; r < NDBC; r++) {
            float w = s_xproj[r * DINNER + d];
            dbc[0][r] += xc0 * w;
            dbc[1][r] += xc1 * w;
            dbc[2][r] += xc2 * w;
        }
    }
#pragma unroll
    for (int l = 0; l < 3; l++)
#pragma unroll
        for (int r = 0; r < NDBC; r++) dbc[l][r] = grp4_sum(dbc[l][r]);

    // ---- SSM over own 8 d-channels, partial o, then reduce --------------------
    float o[3][GD];
#pragma unroll
    for (int l = 0; l < 3; l++)
#pragma unroll
        for (int j = 0; j < GD; j++) o[l][j] = 0.f;

#pragma unroll
    for (int i = 0; i < 8; i++) {
        int d = k * 8 + i;
        float h[DSTATE];
#pragma unroll
        for (int s = 0; s < DSTATE; s++) h[s] = 0.f;

#pragma unroll
        for (int l = 0; l < 3; l++) {
            float dts = softplus_f(dbc[l][0] * s_dtw[d] + s_dtb[d]);
            float xld = xcr[l][i];
            float dtx = dts * xld;
            float yld = 0.f;
#pragma unroll
            for (int s = 0; s < DSTATE; s++) {
                h[s] = __expf(dts * s_A[d * DSTATE + s]) * h[s]
                     + dtx * dbc[l][1 + s];
                yld += h[s] * dbc[l][1 + DSTATE + s];
            }
            yld += s_D[d] * xld;
            float zld = 0.f;
#pragma unroll
            for (int j = 0; j < GD; j++)
                zld += gg[l][j] * s_inproj[(DINNER + d) * GD + j];
            yld *= silu_f(zld);
#pragma unroll
            for (int j = 0; j < GD; j++)
                o[l][j] += yld * s_outproj[j * DINNER + d];
        }
    }
#pragma unroll
    for (int l = 0; l < 3; l++)
#pragma unroll
        for (int j = 0; j < GD; j++) o[l][j] = grp4_sum(o[l][j]);

    // ---- residual + layernorm + logit + softmax (k==0 writes) ----------------
    if (k == 0) {
        float logit[3];
#pragma unroll
        for (int l = 0; l < 3; l++) {
            float y2[GD];
            float mu = 0.f;
#pragma unroll
            for (int j = 0; j < GD; j++) { y2[j] = o[l][j] + gg[l][j]; mu += y2[j]; }
            mu *= (1.f / GD);
            float var = 0.f;
#pragma unroll
            for (int j = 0; j < GD; j++) { float dlt = y2[j] - mu; var += dlt * dlt; }
            var *= (1.f / GD);
            float rstd = rsqrtf(var + 1e-12f);
            float lg = 0.f;
#pragma unroll
            for (int j = 0; j < GD; j++)
                lg += ((y2[j] - mu) * rstd * s_lng[j] + s_lnb[j]) * s_tlw[j];
            logit[l] = lg + s_tlb;
        }
        float mmax = fmaxf(logit[0], fmaxf(logit[1], logit[2]));
        float e0 = __expf((logit[0] - mmax) / TEMP);
        float e1 = __expf((logit[1] - mmax) / TEMP);
        float e2s = __expf((logit[2] - mmax) / TEMP);
        float inv = 1.f / (e0 + e1 + e2s);
        s_w[nl * 3 + 0] = e0 * inv;
        s_w[nl * 3 + 1] = e1 * inv;
        s_w[nl * 3 + 2] = e2s * inv;
    }
    __syncthreads();

    // ---- coalesced float4 output ----------------------------------------------
    const int base = blockIdx.x * NPB;
    for (int i = tid; i < NPB * 16; i += 128) {
        int n  = i >> 4;
        int c4 = (i & 15) * 4;
        int nn = s_nid[n];
        float w0 = s_w[n * 3 + 0], w1 = s_w[n * 3 + 1], w2 = s_w[n * 3 + 2];
        const float* r0 = (nn < N_USER) ? (user + (size_t)nn * D)
                                        : (item + (size_t)(nn - N_USER) * D);
        float4 v0 = *reinterpret_cast<const float4*>(r0 + c4);
        float4 v1 = *reinterpret_cast<const float4*>(g_embA + (size_t)nn * D + c4);
        float4 v2 = *reinterpret_cast<const float4*>(&s_embB[n * 64 + c4]);
        float4 ov;
        ov.x = w0 * v0.x + w1 * v1.x + w2 * v2.x;
        ov.y = w0 * v0.y + w1 * v1.y + w2 * v2.y;
        ov.z = w0 * v0.z + w1 * v1.z + w2 * v2.z;
        ov.w = w0 * v0.w + w1 * v1.w + w2 * v2.w;
        *reinterpret_cast<float4*>(out + (size_t)(base + n) * D + c4) = ov;
    }
}

// ---------------------------------------------------------------------------
// Cleanup (LAST launch): restore zeroed scratch so the next execution/replay
// sees pristine state. Globals are zero-init at module load, so the first
// execution is correct without a front init.
// ---------------------------------------------------------------------------
__global__ void cleanup_kernel() {
    int i = blockIdx.x * blockDim.x + threadIdx.x;
    if (i < NTOT)   g_cnt[i] = 0;
    if (i < NWORDS) { g_need1[i] = 0; g_need2[i] = 0; }
}

// ---------------------------------------------------------------------------
// Launch
// ---------------------------------------------------------------------------
extern "C" void kernel_launch(void* const* d_in, const int* in_sizes, int n_in,
                              void* d_out, int out_size) {
    const float *user, *item, *eval_, *down_w, *in_proj_w, *conv_w, *conv_b,
                *x_proj_w, *dt_proj_w, *dt_proj_b, *A_log, *D_param,
                *out_proj_w, *ln_g, *ln_b, *tl_w, *tl_b;
    const int *erow, *ecol, *nids;

    if (in_sizes[3] == 1024) {
        user      = (const float*)d_in[0];
        item      = (const float*)d_in[1];
        eval_     = (const float*)d_in[2];
        down_w    = (const float*)d_in[3];
        in_proj_w = (const float*)d_in[4];
        conv_w    = (const float*)d_in[5];
        conv_b    = (const float*)d_in[6];
        x_proj_w  = (const float*)d_in[7];
        dt_proj_w = (const float*)d_in[8];
        dt_proj_b = (const float*)d_in[9];
        A_log     = (const float*)d_in[10];
        D_param   = (const float*)d_in[11];
        out_proj_w= (const float*)d_in[12];
        ln_g      = (const float*)d_in[13];
        ln_b      = (const float*)d_in[14];
        tl_w      = (const float*)d_in[15];
        tl_b      = (const float*)d_in[16];
        erow      = (const int*)d_in[17];
        ecol      = (const int*)d_in[18];
        nids      = (const int*)d_in[19];
    } else {
        user      = (const float*)d_in[0];
        item      = (const float*)d_in[1];
        erow      = (const int*)d_in[2];
        ecol      = (const int*)d_in[3];
        eval_     = (const float*)d_in[4];
        nids      = (const int*)d_in[5];
        down_w    = (const float*)d_in[6];
        in_proj_w = (const float*)d_in[7];
        conv_w    = (const float*)d_in[8];
        conv_b    = (const float*)d_in[9];
        x_proj_w  = (const float*)d_in[10];
        dt_proj_w = (const float*)d_in[11];
        dt_proj_b = (const float*)d_in[12];
        A_log     = (const float*)d_in[13];
        D_param   = (const float*)d_in[14];
        out_proj_w= (const float*)d_in[15];
        ln_g      = (const float*)d_in[16];
        ln_b      = (const float*)d_in[17];
        tl_w      = (const float*)d_in[18];
        tl_b      = (const float*)d_in[19];
    }

    mark2_kernel<<<(BATCH + 255) / 256, 256>>>(nids);
    mark1_kernel<<<(NNZ / 4 + 255) / 256, 256>>>(erow, ecol);
    bucket_kernel<<<(NNZ / 4 + 255) / 256, 256>>>(erow, ecol, eval_);

    const int gn_blocks = (NTOT * 16 + 255) / 256;
    gather_norm1_kernel<<<gn_blocks, 256>>>(user, item);

    mamba_fuse_kernel<<<BATCH / NPB, 128>>>(
        user, item, nids, down_w, in_proj_w, conv_w, conv_b, x_proj_w,
        dt_proj_w, dt_proj_b, A_log, D_param, out_proj_w, ln_g, ln_b,
        tl_w, tl_b, (float*)d_out);

    cleanup_kernel<<<(NTOT + 255) / 256, 256>>>();
}